// round 10
// baseline (speedup 1.0000x reference)
#include <cuda_runtime.h>

#define T_LEN   16777216
#define BLOCK   256
#define ITEMS   16
#define TILE    (BLOCK * ITEMS)        // 4096
#define NTILES  (T_LEN / TILE)         // 4096
#define GRID    592                    // 148 SMs x 4 blocks: ALL co-resident
#define NWARP   (BLOCK / 32)           // 8
#define QPT     (TILE / 4 / BLOCK)     // 4 float4 quads per thread
#define SLOTS   1151                   // padded float4 slots (Qmax=1023 -> 1150)
#define FULLMASK 0xffffffffu

// Decoupled-lookback state. NEVER reset: flags are generation-encoded
// (partial = 3*gen+1, inclusive = 3*gen+2, monotone across launches).
// Each CTA bumps g_ctr once per launch; gen = ticket / GRID is identical
// for all CTAs of one launch (launches are sequential in-stream).
__device__ unsigned g_ctr;
__device__ unsigned g_flag[NTILES];
__device__ float g_pA[NTILES], g_pB[NTILES];
__device__ float g_iA[NTILES], g_iB[NTILES];

__global__ __launch_bounds__(BLOCK) void ses_scan(
    const float* __restrict__ y, const float* __restrict__ alpha_p,
    float* __restrict__ out)
{
    // Two padded transpose buffers: float4 slot = Q + (Q>>3).
    // Conflict-free for striped (consecutive Q) and blocked (Q = 4*tid+i).
    __shared__ float4 s4[2][SLOTS];              // 2 x 18.4 KB
    __shared__ float sh_wB[NWARP];
    __shared__ float sh_carry;
    __shared__ unsigned sh_gen;

    const int tid  = threadIdx.x;
    const int lane = tid & 31;
    const int wid  = tid >> 5;
    const int bid  = blockIdx.x;

    if (tid == 0) sh_gen = atomicAdd(&g_ctr, 1u) / GRID;

    const float alpha = __ldg(alpha_p);
    const float a = 1.0f - alpha;
    float a2 = a*a, a4 = a2*a2, a8 = a4*a4;
    const float a16 = a8 * a8;

    // ---- prologue: prefetch first tile into buffer 0 ----
    {
        const float4* yin = reinterpret_cast<const float4*>(y) + (size_t)bid * (TILE / 4);
        #pragma unroll
        for (int j = 0; j < QPT; j++) {
            const int Q = j * BLOCK + tid;
            unsigned sa = (unsigned)__cvta_generic_to_shared(&s4[0][Q + (Q >> 3)]);
            asm volatile("cp.async.cg.shared.global [%0], [%1], 16;\n"
                         :: "r"(sa), "l"(yin + Q) : "memory");
        }
        asm volatile("cp.async.commit_group;\n" ::: "memory");
    }

    int buf = 0;
    for (int tile = bid; tile < NTILES; tile += GRID, buf ^= 1) {
        const int nxt = tile + GRID;

        // ---- prefetch next tile into the other buffer (overlaps everything) ----
        if (nxt < NTILES) {
            const float4* yin = reinterpret_cast<const float4*>(y) + (size_t)nxt * (TILE / 4);
            #pragma unroll
            for (int j = 0; j < QPT; j++) {
                const int Q = j * BLOCK + tid;
                unsigned sa = (unsigned)__cvta_generic_to_shared(&s4[buf ^ 1][Q + (Q >> 3)]);
                asm volatile("cp.async.cg.shared.global [%0], [%1], 16;\n"
                             :: "r"(sa), "l"(yin + Q) : "memory");
            }
            asm volatile("cp.async.commit_group;\n" ::: "memory");
            asm volatile("cp.async.wait_group 1;\n" ::: "memory");  // current tile done
        } else {
            asm volatile("cp.async.wait_group 0;\n" ::: "memory");
        }
        __syncthreads();

        const unsigned gen = sh_gen;
        const unsigned base1 = 3u * gen + 1u;

        // ---- blocked read + thread-local serial scan (zero carry-in) ----
        float v[ITEMS];
        #pragma unroll
        for (int i = 0; i < QPT; i++) {
            const int Q = 4 * tid + i;
            float4 q = s4[buf][Q + (Q >> 3)];
            v[4*i+0] = q.x; v[4*i+1] = q.y; v[4*i+2] = q.z; v[4*i+3] = q.w;
        }
        float B;
        {
            float p = 0.f;
            const bool first = (tile == 0 && tid == 0);
            #pragma unroll
            for (int i = 0; i < ITEMS; i++) {
                float aa = a, bb = alpha * v[i];
                if (first && i == 0) { aa = 0.f; bb = v[0]; }  // pin level_0 = y_0
                p = fmaf(aa, p, bb);
                v[i] = p;
            }
            B = p;
        }

        // ---- warp inclusive scan of B; window-A closed form a^(16d) ----
        float m = a16;
        #pragma unroll
        for (int d = 1; d < 32; d <<= 1) {
            float pB = __shfl_up_sync(FULLMASK, B, d);
            if (lane >= d) B = fmaf(m, pB, B);
            m = m * m;
        }
        const float A512 = m;                    // a^512 = per-warp A
        float exB = __shfl_up_sync(FULLMASK, B, 1);
        if (lane == 0) exB = 0.f;
        if (lane == 31) sh_wB[wid] = B;
        __syncthreads();

        float WB = 0.f;
        #pragma unroll
        for (int w = 0; w < NWARP; w++) if (w < wid) WB = fmaf(A512, WB, sh_wB[w]);

        float exA = 1.f;                         // a^(16*lane)
        { float bp = a16; int e = lane;
          #pragma unroll
          for (int k = 0; k < 5; k++) { if (e & 1) exA *= bp; bp *= bp; e >>= 1; } }
        const float TexB = fmaf(exA, WB, exB);
        float TexA = exA;                        // a^(16*tid); multiplies carry only
        { float wp = A512; int e = wid;
          #pragma unroll
          for (int k = 0; k < 3; k++) { if (e & 1) TexA *= wp; wp *= wp; e >>= 1; } }

        // ---- publish tile aggregate ----
        float aggA = 0.f, aggB = 0.f;
        if (tid == 0) {
            float gB = 0.f;
            #pragma unroll
            for (int w = 0; w < NWARP; w++) gB = fmaf(A512, gB, sh_wB[w]);
            float A4096 = A512 * A512; A4096 *= A4096; A4096 *= A4096;  // a^4096
            aggA = (tile == 0) ? 0.f : A4096;
            aggB = gB;
            if (tile == 0) {
                __stcg(&g_iA[0], 0.f);
                __stcg(&g_iB[0], gB);
                __threadfence();
                atomicExch(&g_flag[0], base1 + 1u);     // inclusive
                sh_carry = 0.f;
            } else {
                __stcg(&g_pA[tile], A4096);
                __stcg(&g_pB[tile], gB);
                __threadfence();
                atomicExch(&g_flag[tile], base1);       // partial
            }
        }

        // ---- warp-parallel decoupled lookback (warp 0), early-exit accA==0 ----
        if (wid == 0 && tile > 0) {
            __syncwarp();
            float accA = 1.f, accB = 0.f;
            int pred = tile - 1;
            for (;;) {
                const int idx = pred - lane;
                unsigned st;
                if (idx >= 0) {
                    unsigned f = *((volatile unsigned*)&g_flag[idx]);
                    while (f < base1) {              // stale gen or unset
                        __nanosleep(32);
                        f = *((volatile unsigned*)&g_flag[idx]);
                    }
                    st = f - base1 + 1u;             // 1=partial 2=inclusive
                } else st = 2u;
                __threadfence();
                float mA, mB;
                if (idx < 0)      { mA = 1.f;                mB = 0.f; }
                else if (st == 2u){ mA = __ldcg(&g_iA[idx]); mB = __ldcg(&g_iB[idx]); }
                else              { mA = __ldcg(&g_pA[idx]); mB = __ldcg(&g_pB[idx]); }

                const unsigned bal = __ballot_sync(FULLMASK, st == 2u);
                const int mm = bal ? (__ffs(bal) - 1) : 32;
                const int start = (mm < 32) ? mm : 31;

                float cA = 1.f, cB = 0.f;            // window earliest->latest
                for (int L = start; L >= 0; --L) {
                    float sA = __shfl_sync(FULLMASK, mA, L);
                    float sB = __shfl_sync(FULLMASK, mB, L);
                    cB = fmaf(sA, cB, sB);
                    cA = cA * sA;
                }
                float nB = fmaf(accA, cB, accB);     // acc = combine(window, acc)
                accA = cA * accA;
                accB = nB;

                if (mm < 32 || accA == 0.0f) break;  // accA==0: exact independence
                pred -= 32;
            }
            if (lane == 0) {
                __stcg(&g_iA[tile], accA * aggA);
                __stcg(&g_iB[tile], fmaf(aggA, accB, aggB));
                __threadfence();
                atomicExch(&g_flag[tile], base1 + 1u);
                sh_carry = accB;
            }
        }
        __syncthreads();

        // ---- fixup ----
        const float c = fmaf(TexA, sh_carry, TexB);
        {
            float cp = c * a;
            #pragma unroll
            for (int i = 0; i < ITEMS; i++) { v[i] += cp; cp *= a; }
        }

        // ---- blocked -> SMEM (same buffer), striped streaming stores ----
        #pragma unroll
        for (int i = 0; i < QPT; i++) {
            const int Q = 4 * tid + i;
            s4[buf][Q + (Q >> 3)] = make_float4(v[4*i+0], v[4*i+1], v[4*i+2], v[4*i+3]);
        }
        __syncthreads();

        {
            float4* o4 = reinterpret_cast<float4*>(out) + (size_t)tile * (TILE / 4);
            if (tile != NTILES - 1) {
                #pragma unroll
                for (int j = 0; j < QPT; j++) {
                    const int Q = j * BLOCK + tid;
                    __stcs(&o4[Q], s4[buf][Q + (Q >> 3)]);
                }
            } else {
                const long long tbase = (long long)tile * TILE;
                #pragma unroll
                for (int j = 0; j < QPT; j++) {
                    const int Q = j * BLOCK + tid;
                    float4 q = s4[buf][Q + (Q >> 3)];
                    const long long g = tbase + 4LL * Q;
                    if (g + 4 <= (long long)(T_LEN - 1)) {
                        __stcs(&o4[Q], q);
                    } else {
                        float* op = out + g;
                        if (g + 0 < (long long)(T_LEN - 1)) op[0] = q.x;
                        if (g + 1 < (long long)(T_LEN - 1)) op[1] = q.y;
                        if (g + 2 < (long long)(T_LEN - 1)) op[2] = q.z;
                        if (g + 3 < (long long)(T_LEN - 1)) op[3] = q.w;
                    }
                }
            }
        }
        __syncthreads();   // buffer 'buf' free for reuse by next-next prefetch
    }
}

extern "C" void kernel_launch(void* const* d_in, const int* in_sizes, int n_in,
                              void* d_out, int out_size) {
    const float* y     = (const float*)d_in[0];   // timeseries, T_LEN fp32
    const float* alpha = (const float*)d_in[1];   // 1 fp32
    float* out = (float*)d_out;                   // T_LEN-1 fp32
    (void)in_sizes; (void)n_in; (void)out_size;

    ses_scan<<<GRID, BLOCK>>>(y, alpha, out);     // persistent, single launch
}